// round 7
// baseline (speedup 1.0000x reference)
#include <cuda_runtime.h>
#include <math_constants.h>

typedef unsigned long long u64;

// Problem constants
#define Bb   16
#define Dd   64
#define Kk   1024
#define HW   4096          // H*W
#define NPTS 65536         // B*H*W
#define QELEMS 4194304     // B*D*H*W

// Tiling
#define KC     128         // codebook chunk in smem
#define NCHUNK (Kk / KC)   // 8
#define TPB    128
#define PPB    256         // 2 points per thread
#define NBLK   (NPTS / PPB)
#define ROWU2  33          // ulonglong2 per row (32 data + 1 pad), 528 B

__device__ float g_partial[NBLK];

// packed dual fp32 FMA (Blackwell FFMA2) — bit-exact 2x fp32
__device__ __forceinline__ u64 fma2(u64 a, u64 b, u64 c) {
    u64 d;
    asm("fma.rn.f32x2 %0, %1, %2, %3;" : "=l"(d) : "l"(a), "l"(b), "l"(c));
    return d;
}
__device__ __forceinline__ u64 packf2(float lo, float hi) {
    u64 r;
    asm("mov.b64 %0, {%1, %2};" : "=l"(r) : "f"(lo), "f"(hi));
    return r;
}
__device__ __forceinline__ void unpackf2(u64 v, float& lo, float& hi) {
    asm("mov.b64 {%0, %1}, %2;" : "=f"(lo), "=f"(hi) : "l"(v));
}

__global__ __launch_bounds__(TPB)
void vq_kernel(const float* __restrict__ x,
               const float* __restrict__ e,
               float* __restrict__ out,
               long long out_size) {
    // es: [KC][33] ulonglong2; each u64 half holds one e value duplicated (e_d, e_d)
    __shared__ ulonglong2 es[KC * ROWU2];
    __shared__ float esn[KC];
    __shared__ float red[TPB];

    const int t  = threadIdx.x;
    const int p0 = blockIdx.x * PPB + t;
    const int p1 = p0 + TPB;

    const int b0 = p0 >> 12, hw0 = p0 & 4095;
    const int b1 = p1 >> 12, hw1 = p1 & 4095;
    const size_t base0 = (size_t)b0 * ((size_t)Dd * HW) + hw0;
    const size_t base1 = (size_t)b1 * ((size_t)Dd * HW) + hw1;

    // Load both feature vectors, packed as f32x2 lanes: xp[d] = (xa_d, xb_d)
    float xa[Dd], xb[Dd];
    u64 xp[Dd];
    #pragma unroll
    for (int j = 0; j < Dd; j++) {
        xa[j] = x[base0 + (size_t)j * HW];
        xb[j] = x[base1 + (size_t)j * HW];
        xp[j] = packf2(xa[j], xb[j]);
    }

    float bda = CUDART_INF_F, bdb = CUDART_INF_F;
    int   bka = 0, bkb = 0;

    for (int c = 0; c < NCHUNK; c++) {
        __syncthreads();
        const int kbase = c * KC;
        // Stage chunk: thread t owns code k = kbase+t; loads its column (coalesced
        // along k), writes duplicated pairs, and computes ||e_k||^2 on the fly.
        {
            float4* dstrow = (float4*)&es[t * ROWU2];
            float nrm = 0.f;
            #pragma unroll
            for (int dd = 0; dd < Dd; dd += 2) {
                float v0 = e[(size_t)dd       * Kk + kbase + t];
                float v1 = e[(size_t)(dd + 1) * Kk + kbase + t];
                dstrow[dd >> 1] = make_float4(v0, v0, v1, v1);
                nrm = fmaf(v0, v0, fmaf(v1, v1, nrm));
            }
            esn[t] = nrm;
        }
        __syncthreads();

        #pragma unroll 1
        for (int k = 0; k < KC; k++) {
            const ulonglong2* ek = &es[k * ROWU2];
            u64 a0 = 0ull, a1 = 0ull, a2 = 0ull, a3 = 0ull;
            #pragma unroll
            for (int j = 0; j < 32; j += 2) {
                ulonglong2 v0 = ek[j];       // (e_{2j} dup, e_{2j+1} dup)
                ulonglong2 v1 = ek[j + 1];
                a0 = fma2(xp[2 * j + 0], v0.x, a0);
                a1 = fma2(xp[2 * j + 1], v0.y, a1);
                a2 = fma2(xp[2 * j + 2], v1.x, a2);
                a3 = fma2(xp[2 * j + 3], v1.y, a3);
            }
            float s0a, s0b, s1a, s1b, s2a, s2b, s3a, s3b;
            unpackf2(a0, s0a, s0b);
            unpackf2(a1, s1a, s1b);
            unpackf2(a2, s2a, s2b);
            unpackf2(a3, s3a, s3b);
            float da = fmaf(-2.f, (s0a + s1a) + (s2a + s3a), esn[k]);
            float db = fmaf(-2.f, (s0b + s1b) + (s2b + s3b), esn[k]);
            int kg = kbase + k;
            if (da < bda) { bda = da; bka = kg; }   // strict <: first-min, argmin order
            if (db < bdb) { bdb = db; bkb = kg; }
        }
    }

    // Epilogue: gather chosen codes, quantized output (== quantized, STE identity),
    // and local squared-error sum
    float lsum = 0.f;
    #pragma unroll
    for (int d = 0; d < Dd; d++) {
        float qa = e[(size_t)d * Kk + bka];
        float qb = e[(size_t)d * Kk + bkb];
        long long oa = (long long)(base0 + (size_t)d * HW);
        long long ob = (long long)(base1 + (size_t)d * HW);
        if (oa < out_size) out[oa] = qa;
        if (ob < out_size) out[ob] = qb;
        float ea = xa[d] - qa;
        float eb = xb[d] - qb;
        lsum = fmaf(ea, ea, lsum);
        lsum = fmaf(eb, eb, lsum);
    }

    // indices (as float) at [QELEMS + 2 + p]
    long long idxoff = (long long)QELEMS + 2;
    if (idxoff + p0 < out_size) out[idxoff + p0] = (float)bka;
    if (idxoff + p1 < out_size) out[idxoff + p1] = (float)bkb;

    // Deterministic block reduction
    red[t] = lsum;
    __syncthreads();
    #pragma unroll
    for (int s = TPB / 2; s > 0; s >>= 1) {
        if (t < s) red[t] += red[t + s];
        __syncthreads();
    }
    if (t == 0) g_partial[blockIdx.x] = red[0];
}

__global__ void loss_kernel(float* __restrict__ out, long long out_size) {
    if (blockIdx.x == 0 && threadIdx.x == 0) {
        double s = 0.0;
        for (int i = 0; i < NBLK; i++) s += (double)g_partial[i];
        float mean = (float)(s / (double)QELEMS);
        long long off = (long long)QELEMS;
        if (off     < out_size) out[off]     = mean;  // dictionary_loss
        if (off + 1 < out_size) out[off + 1] = mean;  // commitment_loss
    }
}

extern "C" void kernel_launch(void* const* d_in, const int* in_sizes, int n_in,
                              void* d_out, int out_size) {
    const float* x = (const float*)d_in[0];
    const float* e = (const float*)d_in[1];
    if (n_in >= 2 && in_sizes[0] == Dd * Kk && in_sizes[1] == QELEMS) {
        const float* tmp = x; x = e; e = tmp;
    }
    float* out = (float*)d_out;
    long long osz = (long long)out_size;

    vq_kernel<<<NBLK, TPB>>>(x, e, out, osz);
    loss_kernel<<<1, 32>>>(out, osz);
}

// round 10
// speedup vs baseline: 1.3638x; 1.3638x over previous
#include <cuda_runtime.h>
#include <cuda_bf16.h>
#include <math_constants.h>

typedef unsigned int u32;

#define Dd     64
#define Kk     1024
#define HW     4096
#define NPTS   65536
#define QELEMS 4194304
#define TPB    128
#define MCTA   64                 // points per CTA
#define NBLK   (NPTS / MCTA)      // 1024
#define NG     128                // 8-code groups
#define CH     16                 // groups staged per chunk
#define NCHUNK (NG / CH)          // 8

// smem byte offsets
#define XS_STRIDE 66
#define OFF_XS   0                              // 64*66*4   = 16896
#define OFF_ESN  16896                          // 1024*4    = 4096
#define OFF_SB   20992                          // 16*384*8  = 49152
#define OFF_BIDX 70144                          // 64*4
#define OFF_RED  70400                          // 128*4
#define SMEM_TOTAL 70912

// B fragments in mma register layout: [(group*3 + split)*4 + kstep]*32 + lane
__device__ __align__(16) uint2 g_bfrag[3 * 128 * 4 * 32];
__device__ float g_enorm[Kk];
__device__ float g_partial[NBLK];

// ---- helpers ----
__device__ __forceinline__ float3 split3(float v) {
    float h = __bfloat162float(__float2bfloat16(v));
    float r1 = v - h;                       // exact (Sterbenz)
    float m = __bfloat162float(__float2bfloat16(r1));
    float l = r1 - m;                       // exact; rounded to bf16 at pack
    return make_float3(h, m, l);
}
__device__ __forceinline__ u32 packbf(float a, float b) {
    __nv_bfloat162 t = __floats2bfloat162_rn(a, b);   // a -> low half
    return *reinterpret_cast<u32*>(&t);
}
__device__ __forceinline__ float pick(float3 f, int s) {
    return s == 0 ? f.x : (s == 1 ? f.y : f.z);
}
__device__ __forceinline__ void mma16816(float& c0, float& c1, float& c2, float& c3,
                                         u32 a0, u32 a1, u32 a2, u32 a3,
                                         u32 b0, u32 b1) {
    asm volatile("mma.sync.aligned.m16n8k16.row.col.f32.bf16.bf16.f32 "
                 "{%0,%1,%2,%3}, {%4,%5,%6,%7}, {%8,%9}, {%0,%1,%2,%3};"
                 : "+f"(c0), "+f"(c1), "+f"(c2), "+f"(c3)
                 : "r"(a0), "r"(a1), "r"(a2), "r"(a3), "r"(b0), "r"(b1));
}

// ---- prep: ||e||^2 ----
__global__ void prep_enorm(const float* __restrict__ e) {
    int k = blockIdx.x * blockDim.x + threadIdx.x;
    if (k < Kk) {
        float s = 0.f;
        #pragma unroll
        for (int d = 0; d < Dd; d++) {
            float v = e[(size_t)d * Kk + k];
            s = fmaf(v, v, s);
        }
        g_enorm[k] = s;
    }
}

// ---- prep: B fragments (split codebook, mma B-register layout) ----
// B[k=d][n=code] = e[d*K + n].  Fragment: n = g*8 + lane/4, k0 = ks*16 + 2*(lane%4);
// reg.x = {k0, k0+1}, reg.y = {k0+8, k0+9}.
__global__ void prep_frag(const float* __restrict__ e) {
    int tid = blockIdx.x * blockDim.x + threadIdx.x;   // 49152 threads
    int lane = tid & 31;
    int ks   = (tid >> 5) & 3;
    int s    = (tid >> 7) % 3;
    int grp  = tid / 384;
    int n  = grp * 8 + (lane >> 2);
    int k0 = ks * 16 + 2 * (lane & 3);
    float3 va = split3(e[(size_t)k0 * Kk + n]);
    float3 vb = split3(e[(size_t)(k0 + 1) * Kk + n]);
    float3 vc = split3(e[(size_t)(k0 + 8) * Kk + n]);
    float3 vd = split3(e[(size_t)(k0 + 9) * Kk + n]);
    g_bfrag[tid] = make_uint2(packbf(pick(va, s), pick(vb, s)),
                              packbf(pick(vc, s), pick(vd, s)));
}

// ---- main: 6-product bf16 mma GEMM + fused exact argmin + outputs ----
__global__ __launch_bounds__(TPB)
void vq_kernel(const float* __restrict__ x,
               const float* __restrict__ e,
               float* __restrict__ out,
               long long out_size) {
    extern __shared__ char smem[];
    float* xs  = (float*)(smem + OFF_XS);      // [64][66] fp32 x tile
    float* esn = (float*)(smem + OFF_ESN);     // [1024] ||e||^2
    uint2* sB  = (uint2*)(smem + OFF_SB);      // staged B fragment chunk
    int*   bidx= (int*)  (smem + OFF_BIDX);
    float* red = (float*)(smem + OFF_RED);

    const int t = threadIdx.x, wid = t >> 5, lane = t & 31;
    const int gr = lane >> 2, tc = lane & 3;

    // stage x tile (coalesced: consecutive lanes -> consecutive points)
    for (int i = t; i < MCTA * Dd; i += TPB) {
        int d = i >> 6, pl = i & 63;
        int p = blockIdx.x * MCTA + pl;
        int b = p >> 12, hw = p & 4095;
        xs[pl * XS_STRIDE + d] = x[(size_t)b * (Dd * HW) + (size_t)d * HW + hw];
    }
    for (int i = t; i < Kk; i += TPB) esn[i] = g_enorm[i];
    __syncthreads();

    // build A fragments: 3 splits x 4 ksteps x 4 regs (held all kernel)
    u32 A[3][4][4];
    const int r0 = wid * 16 + gr;
    #pragma unroll
    for (int ks = 0; ks < 4; ks++) {
        #pragma unroll
        for (int half = 0; half < 2; half++) {
            int k = ks * 16 + 2 * tc + half * 8;
            float2 v0 = *(float2*)&xs[r0 * XS_STRIDE + k];
            float2 v1 = *(float2*)&xs[(r0 + 8) * XS_STRIDE + k];
            float3 s0 = split3(v0.x), s1 = split3(v0.y);
            float3 s2 = split3(v1.x), s3 = split3(v1.y);
            A[0][ks][2 * half + 0] = packbf(s0.x, s1.x);
            A[0][ks][2 * half + 1] = packbf(s2.x, s3.x);
            A[1][ks][2 * half + 0] = packbf(s0.y, s1.y);
            A[1][ks][2 * half + 1] = packbf(s2.y, s3.y);
            A[2][ks][2 * half + 0] = packbf(s0.z, s1.z);
            A[2][ks][2 * half + 1] = packbf(s2.z, s3.z);
        }
    }

    float bdl = CUDART_INF_F, bdh = CUDART_INF_F;
    int   bkl = 0, bkh = 0;

    for (int ch = 0; ch < NCHUNK; ch++) {
        __syncthreads();
        // stage B chunk: 16 groups * 384 uint2 = 3072 uint4
        {
            const uint4* src = (const uint4*)(g_bfrag + (size_t)ch * CH * 384);
            uint4* dst = (uint4*)sB;
            #pragma unroll
            for (int i = 0; i < 24; i++) dst[t + i * TPB] = src[t + i * TPB];
        }
        __syncthreads();

        #pragma unroll 1
        for (int gl = 0; gl < CH; gl++) {
            const uint2* bp = sB + gl * 384 + lane;
            u32 B0[4][2], B1[4][2], B2[4][2];
            #pragma unroll
            for (int ks = 0; ks < 4; ks++) {
                uint2 q0 = bp[(0 * 4 + ks) * 32]; B0[ks][0] = q0.x; B0[ks][1] = q0.y;
                uint2 q1 = bp[(1 * 4 + ks) * 32]; B1[ks][0] = q1.x; B1[ks][1] = q1.y;
                uint2 q2 = bp[(2 * 4 + ks) * 32]; B2[ks][0] = q2.x; B2[ks][1] = q2.y;
            }
            float a0=0.f,a1=0.f,a2=0.f,a3=0.f;   // chain A: hh + hl
            float b0=0.f,b1=0.f,b2=0.f,b3=0.f;   // chain B: hm + lh
            float c0=0.f,c1=0.f,c2=0.f,c3=0.f;   // chain C: mh + mm
            #pragma unroll
            for (int ks = 0; ks < 4; ks++)
                mma16816(a0,a1,a2,a3, A[0][ks][0],A[0][ks][1],A[0][ks][2],A[0][ks][3], B0[ks][0],B0[ks][1]);
            #pragma unroll
            for (int ks = 0; ks < 4; ks++)
                mma16816(b0,b1,b2,b3, A[0][ks][0],A[0][ks][1],A[0][ks][2],A[0][ks][3], B1[ks][0],B1[ks][1]);
            #pragma unroll
            for (int ks = 0; ks < 4; ks++)
                mma16816(c0,c1,c2,c3, A[1][ks][0],A[1][ks][1],A[1][ks][2],A[1][ks][3], B0[ks][0],B0[ks][1]);
            #pragma unroll
            for (int ks = 0; ks < 4; ks++)
                mma16816(a0,a1,a2,a3, A[0][ks][0],A[0][ks][1],A[0][ks][2],A[0][ks][3], B2[ks][0],B2[ks][1]);
            #pragma unroll
            for (int ks = 0; ks < 4; ks++)
                mma16816(b0,b1,b2,b3, A[2][ks][0],A[2][ks][1],A[2][ks][2],A[2][ks][3], B0[ks][0],B0[ks][1]);
            #pragma unroll
            for (int ks = 0; ks < 4; ks++)
                mma16816(c0,c1,c2,c3, A[1][ks][0],A[1][ks][1],A[1][ks][2],A[1][ks][3], B1[ks][0],B1[ks][1]);

            int g = ch * CH + gl;
            float2 en = *(float2*)&esn[g * 8 + 2 * tc];
            float d0 = (a0 + b0) + c0, d1 = (a1 + b1) + c1;
            float d2 = (a2 + b2) + c2, d3 = (a3 + b3) + c3;
            float t0 = fmaf(-2.f, d0, en.x);
            float t1 = fmaf(-2.f, d1, en.y);
            float t2 = fmaf(-2.f, d2, en.x);
            float t3 = fmaf(-2.f, d3, en.y);
            int kg = g * 8 + 2 * tc;
            if (t0 < bdl) { bdl = t0; bkl = kg;     }   // ascending k: first-min
            if (t1 < bdl) { bdl = t1; bkl = kg + 1; }
            if (t2 < bdh) { bdh = t2; bkh = kg;     }
            if (t3 < bdh) { bdh = t3; bkh = kg + 1; }
        }
    }

    // reduce over the 4-lane quad (cols), lexicographic (dist, idx)
    #pragma unroll
    for (int o = 1; o <= 2; o <<= 1) {
        float od = __shfl_xor_sync(0xffffffffu, bdl, o);
        int   ok = __shfl_xor_sync(0xffffffffu, bkl, o);
        if (od < bdl || (od == bdl && ok < bkl)) { bdl = od; bkl = ok; }
        float oh = __shfl_xor_sync(0xffffffffu, bdh, o);
        int   oj = __shfl_xor_sync(0xffffffffu, bkh, o);
        if (oh < bdh || (oh == bdh && oj < bkh)) { bdh = oh; bkh = oj; }
    }
    if (tc == 0) {
        bidx[wid * 16 + gr]     = bkl;   // row gr
        bidx[wid * 16 + gr + 8] = bkh;   // row gr+8
    }
    __syncthreads();

    // epilogue: quantized gather + index + loss partial (exact fp32)
    float lsum = 0.f;
    if (t < MCTA) {
        int p = blockIdx.x * MCTA + t;
        int b = p >> 12, hw = p & 4095;
        size_t xbase = (size_t)b * (Dd * HW) + hw;
        int k = bidx[t];
        #pragma unroll
        for (int d = 0; d < Dd; d++) {
            float q = e[(size_t)d * Kk + k];
            long long o = (long long)(xbase + (size_t)d * HW);
            if (o < out_size) out[o] = q;
            float df = xs[t * XS_STRIDE + d] - q;
            lsum = fmaf(df, df, lsum);
        }
        long long io = (long long)QELEMS + 2 + p;
        if (io < out_size) out[io] = (float)k;
    }
    red[t] = lsum;
    __syncthreads();
    #pragma unroll
    for (int sft = TPB / 2; sft > 0; sft >>= 1) {
        if (t < sft) red[t] += red[t + sft];
        __syncthreads();
    }
    if (t == 0) g_partial[blockIdx.x] = red[0];
}

__global__ void loss_kernel(float* __restrict__ out, long long out_size) {
    if (blockIdx.x == 0 && threadIdx.x == 0) {
        double s = 0.0;
        for (int i = 0; i < NBLK; i++) s += (double)g_partial[i];
        float mean = (float)(s / (double)QELEMS);
        long long off = (long long)QELEMS;
        if (off     < out_size) out[off]     = mean;  // dictionary_loss
        if (off + 1 < out_size) out[off + 1] = mean;  // commitment_loss
    }
}

extern "C" void kernel_launch(void* const* d_in, const int* in_sizes, int n_in,
                              void* d_out, int out_size) {
    const float* x = (const float*)d_in[0];
    const float* e = (const float*)d_in[1];
    if (n_in >= 2 && in_sizes[0] == Dd * Kk && in_sizes[1] == QELEMS) {
        const float* tmp = x; x = e; e = tmp;
    }
    float* out = (float*)d_out;
    long long osz = (long long)out_size;

    cudaFuncSetAttribute(vq_kernel, cudaFuncAttributeMaxDynamicSharedMemorySize, SMEM_TOTAL);
    prep_enorm<<<8, 128>>>(e);
    prep_frag<<<384, 128>>>(e);
    vq_kernel<<<NBLK, TPB, SMEM_TOTAL>>>(x, e, out, osz);
    loss_kernel<<<1, 32>>>(out, osz);
}

// round 11
// speedup vs baseline: 1.9181x; 1.4064x over previous
#include <cuda_runtime.h>
#include <cuda_bf16.h>
#include <math_constants.h>

typedef unsigned int u32;

#define Dd     64
#define Kk     1024
#define HW     4096
#define NPTS   65536
#define QELEMS 4194304
#define TPB    128
#define MCTA   64                 // points per CTA
#define NBLK   (NPTS / MCTA)      // 1024
#define NG     128                // 8-code groups
#define CH     16                 // groups staged per chunk
#define NCHUNK (NG / CH)          // 8

// smem byte offsets
#define XS_STRIDE 66
#define OFF_XS   0                              // 64*66*4   = 16896
#define OFF_ESN  16896                          // 1024*4    = 4096
#define OFF_SB   20992                          // 16*384*8  = 49152
#define OFF_BIDX 70144                          // 64*4
#define OFF_RED  70400                          // 128*4
#define SMEM_TOTAL 70912

// B fragments in mma register layout: [(group*3 + split)*4 + kstep]*32 + lane
__device__ __align__(16) uint2 g_bfrag[3 * 128 * 4 * 32];
__device__ float g_enorm[Kk];
__device__ float g_partial[NBLK];

// ---- helpers ----
__device__ __forceinline__ float3 split3(float v) {
    float h = __bfloat162float(__float2bfloat16(v));
    float r1 = v - h;                       // exact (Sterbenz)
    float m = __bfloat162float(__float2bfloat16(r1));
    float l = r1 - m;                       // exact; rounded to bf16 at pack
    return make_float3(h, m, l);
}
__device__ __forceinline__ u32 packbf(float a, float b) {
    __nv_bfloat162 t = __floats2bfloat162_rn(a, b);   // a -> low half
    return *reinterpret_cast<u32*>(&t);
}
__device__ __forceinline__ float pick(float3 f, int s) {
    return s == 0 ? f.x : (s == 1 ? f.y : f.z);
}
__device__ __forceinline__ void mma16816(float& c0, float& c1, float& c2, float& c3,
                                         u32 a0, u32 a1, u32 a2, u32 a3,
                                         u32 b0, u32 b1) {
    asm volatile("mma.sync.aligned.m16n8k16.row.col.f32.bf16.bf16.f32 "
                 "{%0,%1,%2,%3}, {%4,%5,%6,%7}, {%8,%9}, {%0,%1,%2,%3};"
                 : "+f"(c0), "+f"(c1), "+f"(c2), "+f"(c3)
                 : "r"(a0), "r"(a1), "r"(a2), "r"(a3), "r"(b0), "r"(b1));
}

// ---- prep: ||e||^2 ----
__global__ void prep_enorm(const float* __restrict__ e) {
    int k = blockIdx.x * blockDim.x + threadIdx.x;
    if (k < Kk) {
        float s = 0.f;
        #pragma unroll
        for (int d = 0; d < Dd; d++) {
            float v = e[(size_t)d * Kk + k];
            s = fmaf(v, v, s);
        }
        g_enorm[k] = s;
    }
}

// ---- prep: B fragments (split codebook, mma B-register layout) ----
// B[k=d][n=code] = e[d*K + n].  Fragment: n = g*8 + lane/4, k0 = ks*16 + 2*(lane%4);
// reg.x = {k0, k0+1}, reg.y = {k0+8, k0+9}.
__global__ void prep_frag(const float* __restrict__ e) {
    int tid = blockIdx.x * blockDim.x + threadIdx.x;   // 49152 threads
    int lane = tid & 31;
    int ks   = (tid >> 5) & 3;
    int s    = (tid >> 7) % 3;
    int grp  = tid / 384;
    int n  = grp * 8 + (lane >> 2);
    int k0 = ks * 16 + 2 * (lane & 3);
    float3 va = split3(e[(size_t)k0 * Kk + n]);
    float3 vb = split3(e[(size_t)(k0 + 1) * Kk + n]);
    float3 vc = split3(e[(size_t)(k0 + 8) * Kk + n]);
    float3 vd = split3(e[(size_t)(k0 + 9) * Kk + n]);
    g_bfrag[tid] = make_uint2(packbf(pick(va, s), pick(vb, s)),
                              packbf(pick(vc, s), pick(vd, s)));
}

// ---- main: 6-product bf16 mma GEMM + fused exact argmin + outputs ----
__global__ __launch_bounds__(TPB)
void vq_kernel(const float* __restrict__ x,
               const float* __restrict__ e,
               float* __restrict__ out,
               long long out_size) {
    extern __shared__ char smem[];
    float* xs  = (float*)(smem + OFF_XS);      // [64][66] fp32 x tile
    float* esn = (float*)(smem + OFF_ESN);     // [1024] ||e||^2
    uint2* sB  = (uint2*)(smem + OFF_SB);      // staged B fragment chunk
    int*   bidx= (int*)  (smem + OFF_BIDX);
    float* red = (float*)(smem + OFF_RED);

    const int t = threadIdx.x, wid = t >> 5, lane = t & 31;
    const int gr = lane >> 2, tc = lane & 3;

    // stage x tile (coalesced: consecutive lanes -> consecutive points)
    for (int i = t; i < MCTA * Dd; i += TPB) {
        int d = i >> 6, pl = i & 63;
        int p = blockIdx.x * MCTA + pl;
        int b = p >> 12, hw = p & 4095;
        xs[pl * XS_STRIDE + d] = x[(size_t)b * (Dd * HW) + (size_t)d * HW + hw];
    }
    for (int i = t; i < Kk; i += TPB) esn[i] = g_enorm[i];
    __syncthreads();

    // build A fragments: 3 splits x 4 ksteps x 4 regs (held all kernel)
    u32 A[3][4][4];
    const int r0 = wid * 16 + gr;
    #pragma unroll
    for (int ks = 0; ks < 4; ks++) {
        #pragma unroll
        for (int half = 0; half < 2; half++) {
            int k = ks * 16 + 2 * tc + half * 8;
            float2 v0 = *(float2*)&xs[r0 * XS_STRIDE + k];
            float2 v1 = *(float2*)&xs[(r0 + 8) * XS_STRIDE + k];
            float3 s0 = split3(v0.x), s1 = split3(v0.y);
            float3 s2 = split3(v1.x), s3 = split3(v1.y);
            A[0][ks][2 * half + 0] = packbf(s0.x, s1.x);
            A[0][ks][2 * half + 1] = packbf(s2.x, s3.x);
            A[1][ks][2 * half + 0] = packbf(s0.y, s1.y);
            A[1][ks][2 * half + 1] = packbf(s2.y, s3.y);
            A[2][ks][2 * half + 0] = packbf(s0.z, s1.z);
            A[2][ks][2 * half + 1] = packbf(s2.z, s3.z);
        }
    }

    float bdl = CUDART_INF_F, bdh = CUDART_INF_F;
    int   bkl = 0, bkh = 0;

    for (int ch = 0; ch < NCHUNK; ch++) {
        __syncthreads();
        // stage B chunk: 16 groups * 384 uint2 = 3072 uint4
        {
            const uint4* src = (const uint4*)(g_bfrag + (size_t)ch * CH * 384);
            uint4* dst = (uint4*)sB;
            #pragma unroll
            for (int i = 0; i < 24; i++) dst[t + i * TPB] = src[t + i * TPB];
        }
        __syncthreads();

        #pragma unroll 1
        for (int gl = 0; gl < CH; gl++) {
            const uint2* bp = sB + gl * 384 + lane;
            u32 B0[4][2], B1[4][2], B2[4][2];
            #pragma unroll
            for (int ks = 0; ks < 4; ks++) {
                uint2 q0 = bp[(0 * 4 + ks) * 32]; B0[ks][0] = q0.x; B0[ks][1] = q0.y;
                uint2 q1 = bp[(1 * 4 + ks) * 32]; B1[ks][0] = q1.x; B1[ks][1] = q1.y;
                uint2 q2 = bp[(2 * 4 + ks) * 32]; B2[ks][0] = q2.x; B2[ks][1] = q2.y;
            }
            float a0=0.f,a1=0.f,a2=0.f,a3=0.f;   // chain A: hh + hl
            float b0=0.f,b1=0.f,b2=0.f,b3=0.f;   // chain B: hm + lh
            float c0=0.f,c1=0.f,c2=0.f,c3=0.f;   // chain C: mh + mm
            #pragma unroll
            for (int ks = 0; ks < 4; ks++)
                mma16816(a0,a1,a2,a3, A[0][ks][0],A[0][ks][1],A[0][ks][2],A[0][ks][3], B0[ks][0],B0[ks][1]);
            #pragma unroll
            for (int ks = 0; ks < 4; ks++)
                mma16816(b0,b1,b2,b3, A[0][ks][0],A[0][ks][1],A[0][ks][2],A[0][ks][3], B1[ks][0],B1[ks][1]);
            #pragma unroll
            for (int ks = 0; ks < 4; ks++)
                mma16816(c0,c1,c2,c3, A[1][ks][0],A[1][ks][1],A[1][ks][2],A[1][ks][3], B0[ks][0],B0[ks][1]);
            #pragma unroll
            for (int ks = 0; ks < 4; ks++)
                mma16816(a0,a1,a2,a3, A[0][ks][0],A[0][ks][1],A[0][ks][2],A[0][ks][3], B2[ks][0],B2[ks][1]);
            #pragma unroll
            for (int ks = 0; ks < 4; ks++)
                mma16816(b0,b1,b2,b3, A[2][ks][0],A[2][ks][1],A[2][ks][2],A[2][ks][3], B0[ks][0],B0[ks][1]);
            #pragma unroll
            for (int ks = 0; ks < 4; ks++)
                mma16816(c0,c1,c2,c3, A[1][ks][0],A[1][ks][1],A[1][ks][2],A[1][ks][3], B1[ks][0],B1[ks][1]);

            int g = ch * CH + gl;
            float2 en = *(float2*)&esn[g * 8 + 2 * tc];
            float d0 = (a0 + b0) + c0, d1 = (a1 + b1) + c1;
            float d2 = (a2 + b2) + c2, d3 = (a3 + b3) + c3;
            float t0 = fmaf(-2.f, d0, en.x);
            float t1 = fmaf(-2.f, d1, en.y);
            float t2 = fmaf(-2.f, d2, en.x);
            float t3 = fmaf(-2.f, d3, en.y);
            int kg = g * 8 + 2 * tc;
            if (t0 < bdl) { bdl = t0; bkl = kg;     }   // ascending k: first-min
            if (t1 < bdl) { bdl = t1; bkl = kg + 1; }
            if (t2 < bdh) { bdh = t2; bkh = kg;     }
            if (t3 < bdh) { bdh = t3; bkh = kg + 1; }
        }
    }

    // reduce over the 4-lane quad (cols), lexicographic (dist, idx)
    #pragma unroll
    for (int o = 1; o <= 2; o <<= 1) {
        float od = __shfl_xor_sync(0xffffffffu, bdl, o);
        int   ok = __shfl_xor_sync(0xffffffffu, bkl, o);
        if (od < bdl || (od == bdl && ok < bkl)) { bdl = od; bkl = ok; }
        float oh = __shfl_xor_sync(0xffffffffu, bdh, o);
        int   oj = __shfl_xor_sync(0xffffffffu, bkh, o);
        if (oh < bdh || (oh == bdh && oj < bkh)) { bdh = oh; bkh = oj; }
    }
    if (tc == 0) {
        bidx[wid * 16 + gr]     = bkl;   // row gr
        bidx[wid * 16 + gr + 8] = bkh;   // row gr+8
    }
    __syncthreads();

    // epilogue: quantized gather + index + loss partial (exact fp32)
    float lsum = 0.f;
    if (t < MCTA) {
        int p = blockIdx.x * MCTA + t;
        int b = p >> 12, hw = p & 4095;
        size_t xbase = (size_t)b * (Dd * HW) + hw;
        int k = bidx[t];
        #pragma unroll
        for (int d = 0; d < Dd; d++) {
            float q = e[(size_t)d * Kk + k];
            long long o = (long long)(xbase + (size_t)d * HW);
            if (o < out_size) out[o] = q;
            float df = xs[t * XS_STRIDE + d] - q;
            lsum = fmaf(df, df, lsum);
        }
        long long io = (long long)QELEMS + 2 + p;
        if (io < out_size) out[io] = (float)k;
    }
    red[t] = lsum;
    __syncthreads();
    #pragma unroll
    for (int sft = TPB / 2; sft > 0; sft >>= 1) {
        if (t < sft) red[t] += red[t + sft];
        __syncthreads();
    }
    if (t == 0) g_partial[blockIdx.x] = red[0];
}

// parallel deterministic loss reduction: 256 threads, fixed-order tree in double
__global__ void loss_kernel(float* __restrict__ out, long long out_size) {
    __shared__ double sred[256];
    int t = threadIdx.x;
    double s = 0.0;
    #pragma unroll
    for (int i = 0; i < NBLK / 256; i++)          // fixed order: 4 sequential adds
        s += (double)g_partial[t + i * 256];
    sred[t] = s;
    __syncthreads();
    #pragma unroll
    for (int sft = 128; sft > 0; sft >>= 1) {     // fixed-order pairwise tree
        if (t < sft) sred[t] += sred[t + sft];
        __syncthreads();
    }
    if (t == 0) {
        float mean = (float)(sred[0] / (double)QELEMS);
        long long off = (long long)QELEMS;
        if (off     < out_size) out[off]     = mean;  // dictionary_loss
        if (off + 1 < out_size) out[off + 1] = mean;  // commitment_loss
    }
}

extern "C" void kernel_launch(void* const* d_in, const int* in_sizes, int n_in,
                              void* d_out, int out_size) {
    const float* x = (const float*)d_in[0];
    const float* e = (const float*)d_in[1];
    if (n_in >= 2 && in_sizes[0] == Dd * Kk && in_sizes[1] == QELEMS) {
        const float* tmp = x; x = e; e = tmp;
    }
    float* out = (float*)d_out;
    long long osz = (long long)out_size;

    cudaFuncSetAttribute(vq_kernel, cudaFuncAttributeMaxDynamicSharedMemorySize, SMEM_TOTAL);
    prep_enorm<<<8, 128>>>(e);
    prep_frag<<<384, 128>>>(e);
    vq_kernel<<<NBLK, TPB, SMEM_TOTAL>>>(x, e, out, osz);
    loss_kernel<<<1, 256>>>(out, osz);
}

// round 12
// speedup vs baseline: 2.9286x; 1.5268x over previous
#include <cuda_runtime.h>
#include <cuda_fp16.h>
#include <math_constants.h>

typedef unsigned int u32;

#define Dd     64
#define Kk     1024
#define HW     4096
#define NPTS   65536
#define QELEMS 4194304
#define TPB    128
#define MCTA   64                 // points per CTA
#define NBLK   (NPTS / MCTA)      // 1024
#define NG     128                // 8-code groups
#define CH     16                 // groups staged per chunk
#define NCHUNK (NG / CH)          // 8
#define INV2048 4.8828125e-4f

// smem byte offsets
#define XS_STRIDE 66
#define OFF_XS   0                              // 64*66*4   = 16896
#define OFF_ESN  16896                          // 1024*4    = 4096
#define OFF_SB   20992                          // 16*256*8  = 32768
#define OFF_BIDX 53760                          // 64*4
#define OFF_RED  54016                          // 128*4
#define SMEM_TOTAL 54592

// B fragments in mma register layout: [(group*2 + split)*4 + kstep]*32 + lane
__device__ __align__(16) uint2 g_bfrag[2 * 128 * 4 * 32];
__device__ float g_enorm[Kk];
__device__ float g_partial[NBLK];

// ---- helpers ----
// fp16 2-split: v = h + m*2^-11 (+ ~2^-22 residual); m' = (v-h)*2048 is exact
__device__ __forceinline__ float2 split2(float v) {
    float h = __half2float(__float2half_rn(v));
    float m = (v - h) * 2048.0f;     // exact: Sterbenz diff, pow2 scale
    return make_float2(h, m);
}
__device__ __forceinline__ u32 packh(float a, float b) {
    __half2 t = __floats2half2_rn(a, b);   // a -> low half
    return *reinterpret_cast<u32*>(&t);
}
__device__ __forceinline__ void mma16816(float& c0, float& c1, float& c2, float& c3,
                                         u32 a0, u32 a1, u32 a2, u32 a3,
                                         u32 b0, u32 b1) {
    asm volatile("mma.sync.aligned.m16n8k16.row.col.f32.f16.f16.f32 "
                 "{%0,%1,%2,%3}, {%4,%5,%6,%7}, {%8,%9}, {%0,%1,%2,%3};"
                 : "+f"(c0), "+f"(c1), "+f"(c2), "+f"(c3)
                 : "r"(a0), "r"(a1), "r"(a2), "r"(a3), "r"(b0), "r"(b1));
}

// ---- prep: ||e||^2 ----
__global__ void prep_enorm(const float* __restrict__ e) {
    int k = blockIdx.x * blockDim.x + threadIdx.x;
    if (k < Kk) {
        float s = 0.f;
        #pragma unroll
        for (int d = 0; d < Dd; d++) {
            float v = e[(size_t)d * Kk + k];
            s = fmaf(v, v, s);
        }
        g_enorm[k] = s;
    }
}

// ---- prep: B fragments (fp16 2-split codebook, mma B-register layout) ----
// B[k=d][n=code] = e[d*K + n].  n = g*8 + lane/4, k0 = ks*16 + 2*(lane%4);
// reg.x = {k0, k0+1}, reg.y = {k0+8, k0+9}.  tid == frag linear index.
__global__ void prep_frag(const float* __restrict__ e) {
    int tid = blockIdx.x * blockDim.x + threadIdx.x;   // 32768 threads
    int lane = tid & 31;
    int ks   = (tid >> 5) & 3;
    int s    = (tid >> 7) & 1;
    int grp  = tid >> 8;
    int n  = grp * 8 + (lane >> 2);
    int k0 = ks * 16 + 2 * (lane & 3);
    float2 va = split2(e[(size_t)k0 * Kk + n]);
    float2 vb = split2(e[(size_t)(k0 + 1) * Kk + n]);
    float2 vc = split2(e[(size_t)(k0 + 8) * Kk + n]);
    float2 vd = split2(e[(size_t)(k0 + 9) * Kk + n]);
    g_bfrag[tid] = (s == 0)
        ? make_uint2(packh(va.x, vb.x), packh(vc.x, vd.x))
        : make_uint2(packh(va.y, vb.y), packh(vc.y, vd.y));
}

// ---- main: 4-product fp16 mma GEMM + fused exact argmin + outputs ----
__global__ __launch_bounds__(TPB)
void vq_kernel(const float* __restrict__ x,
               const float* __restrict__ e,
               float* __restrict__ out,
               long long out_size) {
    extern __shared__ char smem[];
    float* xs  = (float*)(smem + OFF_XS);      // [64][66] fp32 x tile
    float* esn = (float*)(smem + OFF_ESN);     // [1024] ||e||^2
    uint2* sB  = (uint2*)(smem + OFF_SB);      // staged B fragment chunk
    int*   bidx= (int*)  (smem + OFF_BIDX);
    float* red = (float*)(smem + OFF_RED);

    const int t = threadIdx.x, wid = t >> 5, lane = t & 31;
    const int gr = lane >> 2, tc = lane & 3;

    // stage x tile (coalesced: consecutive lanes -> consecutive points)
    for (int i = t; i < MCTA * Dd; i += TPB) {
        int d = i >> 6, pl = i & 63;
        int p = blockIdx.x * MCTA + pl;
        int b = p >> 12, hw = p & 4095;
        xs[pl * XS_STRIDE + d] = x[(size_t)b * (Dd * HW) + (size_t)d * HW + hw];
    }
    for (int i = t; i < Kk; i += TPB) esn[i] = g_enorm[i];
    __syncthreads();

    // build A fragments: 2 splits x 4 ksteps x 4 regs (held all kernel)
    u32 A[2][4][4];
    const int r0 = wid * 16 + gr;
    #pragma unroll
    for (int ks = 0; ks < 4; ks++) {
        #pragma unroll
        for (int half = 0; half < 2; half++) {
            int k = ks * 16 + 2 * tc + half * 8;
            float2 v0 = *(float2*)&xs[r0 * XS_STRIDE + k];
            float2 v1 = *(float2*)&xs[(r0 + 8) * XS_STRIDE + k];
            float2 s0 = split2(v0.x), s1 = split2(v0.y);
            float2 s2 = split2(v1.x), s3 = split2(v1.y);
            A[0][ks][2 * half + 0] = packh(s0.x, s1.x);
            A[0][ks][2 * half + 1] = packh(s2.x, s3.x);
            A[1][ks][2 * half + 0] = packh(s0.y, s1.y);
            A[1][ks][2 * half + 1] = packh(s2.y, s3.y);
        }
    }

    float bdl = CUDART_INF_F, bdh = CUDART_INF_F;
    int   bkl = 0, bkh = 0;

    for (int ch = 0; ch < NCHUNK; ch++) {
        __syncthreads();
        // stage B chunk: 16 groups * 256 uint2 = 2048 uint4
        {
            const uint4* src = (const uint4*)(g_bfrag + (size_t)ch * CH * 256);
            uint4* dst = (uint4*)sB;
            #pragma unroll
            for (int i = 0; i < 16; i++) dst[t + i * TPB] = src[t + i * TPB];
        }
        __syncthreads();

        #pragma unroll 1
        for (int gl = 0; gl < CH; gl++) {
            const uint2* bp = sB + gl * 256 + lane;
            u32 B0[4][2], B1[4][2];
            #pragma unroll
            for (int ks = 0; ks < 4; ks++) {
                uint2 q0 = bp[ks * 32];        B0[ks][0] = q0.x; B0[ks][1] = q0.y;
                uint2 q1 = bp[(4 + ks) * 32];  B1[ks][0] = q1.x; B1[ks][1] = q1.y;
            }
            float a0=0.f,a1=0.f,a2=0.f,a3=0.f;   // hh
            float b0=0.f,b1=0.f,b2=0.f,b3=0.f;   // hm
            float c0=0.f,c1=0.f,c2=0.f,c3=0.f;   // mh
            float d0=0.f,d1=0.f,d2=0.f,d3=0.f;   // mm
            #pragma unroll
            for (int ks = 0; ks < 4; ks++)
                mma16816(a0,a1,a2,a3, A[0][ks][0],A[0][ks][1],A[0][ks][2],A[0][ks][3], B0[ks][0],B0[ks][1]);
            #pragma unroll
            for (int ks = 0; ks < 4; ks++)
                mma16816(b0,b1,b2,b3, A[0][ks][0],A[0][ks][1],A[0][ks][2],A[0][ks][3], B1[ks][0],B1[ks][1]);
            #pragma unroll
            for (int ks = 0; ks < 4; ks++)
                mma16816(c0,c1,c2,c3, A[1][ks][0],A[1][ks][1],A[1][ks][2],A[1][ks][3], B0[ks][0],B0[ks][1]);
            #pragma unroll
            for (int ks = 0; ks < 4; ks++)
                mma16816(d0,d1,d2,d3, A[1][ks][0],A[1][ks][1],A[1][ks][2],A[1][ks][3], B1[ks][0],B1[ks][1]);

            int g = ch * CH + gl;
            float2 en = *(float2*)&esn[g * 8 + 2 * tc];
            // dot = hh + 2^-11*((hm+mh) + 2^-11*mm)
            float e0 = fmaf(fmaf(d0, INV2048, b0 + c0), INV2048, a0);
            float e1 = fmaf(fmaf(d1, INV2048, b1 + c1), INV2048, a1);
            float e2 = fmaf(fmaf(d2, INV2048, b2 + c2), INV2048, a2);
            float e3 = fmaf(fmaf(d3, INV2048, b3 + c3), INV2048, a3);
            float t0 = fmaf(-2.f, e0, en.x);
            float t1 = fmaf(-2.f, e1, en.y);
            float t2 = fmaf(-2.f, e2, en.x);
            float t3 = fmaf(-2.f, e3, en.y);
            int kg = g * 8 + 2 * tc;
            if (t0 < bdl) { bdl = t0; bkl = kg;     }   // ascending k: first-min
            if (t1 < bdl) { bdl = t1; bkl = kg + 1; }
            if (t2 < bdh) { bdh = t2; bkh = kg;     }
            if (t3 < bdh) { bdh = t3; bkh = kg + 1; }
        }
    }

    // reduce over the 4-lane quad (cols), lexicographic (dist, idx)
    #pragma unroll
    for (int o = 1; o <= 2; o <<= 1) {
        float od = __shfl_xor_sync(0xffffffffu, bdl, o);
        int   ok = __shfl_xor_sync(0xffffffffu, bkl, o);
        if (od < bdl || (od == bdl && ok < bkl)) { bdl = od; bkl = ok; }
        float oh = __shfl_xor_sync(0xffffffffu, bdh, o);
        int   oj = __shfl_xor_sync(0xffffffffu, bkh, o);
        if (oh < bdh || (oh == bdh && oj < bkh)) { bdh = oh; bkh = oj; }
    }
    if (tc == 0) {
        bidx[wid * 16 + gr]     = bkl;   // row gr
        bidx[wid * 16 + gr + 8] = bkh;   // row gr+8
    }
    __syncthreads();

    // epilogue: quantized gather + index + loss partial (exact fp32)
    float lsum = 0.f;
    if (t < MCTA) {
        int p = blockIdx.x * MCTA + t;
        int b = p >> 12, hw = p & 4095;
        size_t xbase = (size_t)b * (Dd * HW) + hw;
        int k = bidx[t];
        #pragma unroll
        for (int d = 0; d < Dd; d++) {
            float q = e[(size_t)d * Kk + k];
            long long o = (long long)(xbase + (size_t)d * HW);
            if (o < out_size) out[o] = q;
            float df = xs[t * XS_STRIDE + d] - q;
            lsum = fmaf(df, df, lsum);
        }
        long long io = (long long)QELEMS + 2 + p;
        if (io < out_size) out[io] = (float)k;
    }
    red[t] = lsum;
    __syncthreads();
    #pragma unroll
    for (int sft = TPB / 2; sft > 0; sft >>= 1) {
        if (t < sft) red[t] += red[t + sft];
        __syncthreads();
    }
    if (t == 0) g_partial[blockIdx.x] = red[0];
}

// parallel deterministic loss reduction: 256 threads, fixed-order tree in double
__global__ void loss_kernel(float* __restrict__ out, long long out_size) {
    __shared__ double sred[256];
    int t = threadIdx.x;
    double s = 0.0;
    #pragma unroll
    for (int i = 0; i < NBLK / 256; i++)
        s += (double)g_partial[t + i * 256];
    sred[t] = s;
    __syncthreads();
    #pragma unroll
    for (int sft = 128; sft > 0; sft >>= 1) {
        if (t < sft) sred[t] += sred[t + sft];
        __syncthreads();
    }
    if (t == 0) {
        float mean = (float)(sred[0] / (double)QELEMS);
        long long off = (long long)QELEMS;
        if (off     < out_size) out[off]     = mean;  // dictionary_loss
        if (off + 1 < out_size) out[off + 1] = mean;  // commitment_loss
    }
}

extern "C" void kernel_launch(void* const* d_in, const int* in_sizes, int n_in,
                              void* d_out, int out_size) {
    const float* x = (const float*)d_in[0];
    const float* e = (const float*)d_in[1];
    if (n_in >= 2 && in_sizes[0] == Dd * Kk && in_sizes[1] == QELEMS) {
        const float* tmp = x; x = e; e = tmp;
    }
    float* out = (float*)d_out;
    long long osz = (long long)out_size;

    cudaFuncSetAttribute(vq_kernel, cudaFuncAttributeMaxDynamicSharedMemorySize, SMEM_TOTAL);
    prep_enorm<<<8, 128>>>(e);
    prep_frag<<<256, 128>>>(e);
    vq_kernel<<<NBLK, TPB, SMEM_TOTAL>>>(x, e, out, osz);
    loss_kernel<<<1, 256>>>(out, osz);
}

// round 13
// speedup vs baseline: 3.1311x; 1.0692x over previous
#include <cuda_runtime.h>
#include <cuda_fp16.h>
#include <math_constants.h>

typedef unsigned int u32;

#define Dd     64
#define Kk     1024
#define HW     4096
#define NPTS   65536
#define QELEMS 4194304
#define TPB    128
#define MCTA   64                 // points per CTA
#define NBLK   (NPTS / MCTA)      // 1024
#define NG     128                // 8-code groups
#define CH     16                 // groups staged per chunk
#define NCHUNK (NG / CH)          // 8
#define INV2048 4.8828125e-4f

// smem byte offsets
#define XS_STRIDE 66
#define OFF_XS   0                              // 64*66*4   = 16896
#define OFF_ESN  16896                          // 1024*4    = 4096
#define OFF_SB   20992                          // 16*256*8  = 32768
#define OFF_BIDX 53760                          // 64*4
#define OFF_RED  54016                          // 128*4
#define SMEM_TOTAL 54592

// B fragments in mma register layout: [(group*2 + split)*4 + kstep]*32 + lane
__device__ __align__(16) uint2 g_bfrag[2 * 128 * 4 * 32];
__device__ float g_enorm[Kk];
__device__ float g_partial[NBLK];

// ---- helpers ----
// fp16 2-split: v = h + m*2^-11 (+ ~2^-22 residual); m' = (v-h)*2048 is exact
__device__ __forceinline__ float2 split2(float v) {
    float h = __half2float(__float2half_rn(v));
    float m = (v - h) * 2048.0f;     // exact: Sterbenz diff, pow2 scale
    return make_float2(h, m);
}
__device__ __forceinline__ u32 packh(float a, float b) {
    __half2 t = __floats2half2_rn(a, b);   // a -> low half
    return *reinterpret_cast<u32*>(&t);
}
__device__ __forceinline__ void mma16816(float& c0, float& c1, float& c2, float& c3,
                                         u32 a0, u32 a1, u32 a2, u32 a3,
                                         u32 b0, u32 b1) {
    asm volatile("mma.sync.aligned.m16n8k16.row.col.f32.f16.f16.f32 "
                 "{%0,%1,%2,%3}, {%4,%5,%6,%7}, {%8,%9}, {%0,%1,%2,%3};"
                 : "+f"(c0), "+f"(c1), "+f"(c2), "+f"(c3)
                 : "r"(a0), "r"(a1), "r"(a2), "r"(a3), "r"(b0), "r"(b1));
}

// ---- prep: ||e||^2 ----
__global__ void prep_enorm(const float* __restrict__ e) {
    int k = blockIdx.x * blockDim.x + threadIdx.x;
    if (k < Kk) {
        float s = 0.f;
        #pragma unroll
        for (int d = 0; d < Dd; d++) {
            float v = e[(size_t)d * Kk + k];
            s = fmaf(v, v, s);
        }
        g_enorm[k] = s;
    }
}

// ---- prep: B fragments (fp16 2-split codebook, mma B-register layout) ----
// B[k=d][n=code] = e[d*K + n].  n = g*8 + lane/4, k0 = ks*16 + 2*(lane%4);
// reg.x = {k0, k0+1}, reg.y = {k0+8, k0+9}.  tid == frag linear index.
__global__ void prep_frag(const float* __restrict__ e) {
    int tid = blockIdx.x * blockDim.x + threadIdx.x;   // 32768 threads
    int lane = tid & 31;
    int ks   = (tid >> 5) & 3;
    int s    = (tid >> 7) & 1;
    int grp  = tid >> 8;
    int n  = grp * 8 + (lane >> 2);
    int k0 = ks * 16 + 2 * (lane & 3);
    float2 va = split2(e[(size_t)k0 * Kk + n]);
    float2 vb = split2(e[(size_t)(k0 + 1) * Kk + n]);
    float2 vc = split2(e[(size_t)(k0 + 8) * Kk + n]);
    float2 vd = split2(e[(size_t)(k0 + 9) * Kk + n]);
    g_bfrag[tid] = (s == 0)
        ? make_uint2(packh(va.x, vb.x), packh(vc.x, vd.x))
        : make_uint2(packh(va.y, vb.y), packh(vc.y, vd.y));
}

// ---- main: 3-product fp16 mma GEMM + fused argmin + outputs ----
__global__ __launch_bounds__(TPB)
void vq_kernel(const float* __restrict__ x,
               const float* __restrict__ e,
               float* __restrict__ out,
               long long out_size) {
    extern __shared__ char smem[];
    float* xs  = (float*)(smem + OFF_XS);      // [64][66] fp32 x tile
    float* esn = (float*)(smem + OFF_ESN);     // [1024] ||e||^2
    uint2* sB  = (uint2*)(smem + OFF_SB);      // staged B fragment chunk
    int*   bidx= (int*)  (smem + OFF_BIDX);
    float* red = (float*)(smem + OFF_RED);

    const int t = threadIdx.x, wid = t >> 5, lane = t & 31;
    const int gr = lane >> 2, tc = lane & 3;

    // stage x tile (coalesced: consecutive lanes -> consecutive points)
    for (int i = t; i < MCTA * Dd; i += TPB) {
        int d = i >> 6, pl = i & 63;
        int p = blockIdx.x * MCTA + pl;
        int b = p >> 12, hw = p & 4095;
        xs[pl * XS_STRIDE + d] = x[(size_t)b * (Dd * HW) + (size_t)d * HW + hw];
    }
    for (int i = t; i < Kk; i += TPB) esn[i] = g_enorm[i];
    __syncthreads();

    // build A fragments: 2 splits x 4 ksteps x 4 regs (held all kernel)
    u32 A[2][4][4];
    const int r0 = wid * 16 + gr;
    #pragma unroll
    for (int ks = 0; ks < 4; ks++) {
        #pragma unroll
        for (int half = 0; half < 2; half++) {
            int k = ks * 16 + 2 * tc + half * 8;
            float2 v0 = *(float2*)&xs[r0 * XS_STRIDE + k];
            float2 v1 = *(float2*)&xs[(r0 + 8) * XS_STRIDE + k];
            float2 s0 = split2(v0.x), s1 = split2(v0.y);
            float2 s2 = split2(v1.x), s3 = split2(v1.y);
            A[0][ks][2 * half + 0] = packh(s0.x, s1.x);
            A[0][ks][2 * half + 1] = packh(s2.x, s3.x);
            A[1][ks][2 * half + 0] = packh(s0.y, s1.y);
            A[1][ks][2 * half + 1] = packh(s2.y, s3.y);
        }
    }

    float bdl = CUDART_INF_F, bdh = CUDART_INF_F;
    int   bkl = 0, bkh = 0;

    for (int ch = 0; ch < NCHUNK; ch++) {
        __syncthreads();
        // stage B chunk: 16 groups * 256 uint2 = 2048 uint4
        {
            const uint4* src = (const uint4*)(g_bfrag + (size_t)ch * CH * 256);
            uint4* dst = (uint4*)sB;
            #pragma unroll
            for (int i = 0; i < 16; i++) dst[t + i * TPB] = src[t + i * TPB];
        }
        __syncthreads();

        #pragma unroll 1
        for (int gl = 0; gl < CH; gl++) {
            const uint2* bp = sB + gl * 256 + lane;
            u32 B0[4][2], B1[4][2];
            #pragma unroll
            for (int ks = 0; ks < 4; ks++) {
                uint2 q0 = bp[ks * 32];        B0[ks][0] = q0.x; B0[ks][1] = q0.y;
                uint2 q1 = bp[(4 + ks) * 32];  B1[ks][0] = q1.x; B1[ks][1] = q1.y;
            }
            float a0=0.f,a1=0.f,a2=0.f,a3=0.f;   // hh
            float b0=0.f,b1=0.f,b2=0.f,b3=0.f;   // hm
            float c0=0.f,c1=0.f,c2=0.f,c3=0.f;   // mh
            #pragma unroll
            for (int ks = 0; ks < 4; ks++)
                mma16816(a0,a1,a2,a3, A[0][ks][0],A[0][ks][1],A[0][ks][2],A[0][ks][3], B0[ks][0],B0[ks][1]);
            #pragma unroll
            for (int ks = 0; ks < 4; ks++)
                mma16816(b0,b1,b2,b3, A[0][ks][0],A[0][ks][1],A[0][ks][2],A[0][ks][3], B1[ks][0],B1[ks][1]);
            #pragma unroll
            for (int ks = 0; ks < 4; ks++)
                mma16816(c0,c1,c2,c3, A[1][ks][0],A[1][ks][1],A[1][ks][2],A[1][ks][3], B0[ks][0],B0[ks][1]);

            int g = ch * CH + gl;
            float2 en = *(float2*)&esn[g * 8 + 2 * tc];
            // dot = hh + 2^-11*(hm + mh)   (mm term ~2^-22, dropped)
            float e0 = fmaf(b0 + c0, INV2048, a0);
            float e1 = fmaf(b1 + c1, INV2048, a1);
            float e2 = fmaf(b2 + c2, INV2048, a2);
            float e3 = fmaf(b3 + c3, INV2048, a3);
            float t0 = fmaf(-2.f, e0, en.x);
            float t1 = fmaf(-2.f, e1, en.y);
            float t2 = fmaf(-2.f, e2, en.x);
            float t3 = fmaf(-2.f, e3, en.y);
            int kg = g * 8 + 2 * tc;
            if (t0 < bdl) { bdl = t0; bkl = kg;     }   // ascending k: first-min
            if (t1 < bdl) { bdl = t1; bkl = kg + 1; }
            if (t2 < bdh) { bdh = t2; bkh = kg;     }
            if (t3 < bdh) { bdh = t3; bkh = kg + 1; }
        }
    }

    // reduce over the 4-lane quad (cols), lexicographic (dist, idx)
    #pragma unroll
    for (int o = 1; o <= 2; o <<= 1) {
        float od = __shfl_xor_sync(0xffffffffu, bdl, o);
        int   ok = __shfl_xor_sync(0xffffffffu, bkl, o);
        if (od < bdl || (od == bdl && ok < bkl)) { bdl = od; bkl = ok; }
        float oh = __shfl_xor_sync(0xffffffffu, bdh, o);
        int   oj = __shfl_xor_sync(0xffffffffu, bkh, o);
        if (oh < bdh || (oh == bdh && oj < bkh)) { bdh = oh; bkh = oj; }
    }
    if (tc == 0) {
        bidx[wid * 16 + gr]     = bkl;   // row gr
        bidx[wid * 16 + gr + 8] = bkh;   // row gr+8
    }
    __syncthreads();

    // epilogue: quantized gather + index + loss partial (exact fp32)
    float lsum = 0.f;
    if (t < MCTA) {
        int p = blockIdx.x * MCTA + t;
        int b = p >> 12, hw = p & 4095;
        size_t xbase = (size_t)b * (Dd * HW) + hw;
        int k = bidx[t];
        #pragma unroll
        for (int d = 0; d < Dd; d++) {
            float q = e[(size_t)d * Kk + k];
            long long o = (long long)(xbase + (size_t)d * HW);
            if (o < out_size) out[o] = q;
            float df = xs[t * XS_STRIDE + d] - q;
            lsum = fmaf(df, df, lsum);
        }
        long long io = (long long)QELEMS + 2 + p;
        if (io < out_size) out[io] = (float)k;
    }
    red[t] = lsum;
    __syncthreads();
    #pragma unroll
    for (int sft = TPB / 2; sft > 0; sft >>= 1) {
        if (t < sft) red[t] += red[t + sft];
        __syncthreads();
    }
    if (t == 0) g_partial[blockIdx.x] = red[0];
}

// parallel deterministic loss reduction: 256 threads, fixed-order tree in double
__global__ void loss_kernel(float* __restrict__ out, long long out_size) {
    __shared__ double sred[256];
    int t = threadIdx.x;
    double s = 0.0;
    #pragma unroll
    for (int i = 0; i < NBLK / 256; i++)
        s += (double)g_partial[t + i * 256];
    sred[t] = s;
    __syncthreads();
    #pragma unroll
    for (int sft = 128; sft > 0; sft >>= 1) {
        if (t < sft) sred[t] += sred[t + sft];
        __syncthreads();
    }
    if (t == 0) {
        float mean = (float)(sred[0] / (double)QELEMS);
        long long off = (long long)QELEMS;
        if (off     < out_size) out[off]     = mean;  // dictionary_loss
        if (off + 1 < out_size) out[off + 1] = mean;  // commitment_loss
    }
}

extern "C" void kernel_launch(void* const* d_in, const int* in_sizes, int n_in,
                              void* d_out, int out_size) {
    const float* x = (const float*)d_in[0];
    const float* e = (const float*)d_in[1];
    if (n_in >= 2 && in_sizes[0] == Dd * Kk && in_sizes[1] == QELEMS) {
        const float* tmp = x; x = e; e = tmp;
    }
    float* out = (float*)d_out;
    long long osz = (long long)out_size;

    cudaFuncSetAttribute(vq_kernel, cudaFuncAttributeMaxDynamicSharedMemorySize, SMEM_TOTAL);
    prep_enorm<<<8, 128>>>(e);
    prep_frag<<<256, 128>>>(e);
    vq_kernel<<<NBLK, TPB, SMEM_TOTAL>>>(x, e, out, osz);
    loss_kernel<<<1, 256>>>(out, osz);
}

// round 14
// speedup vs baseline: 3.5337x; 1.1286x over previous
#include <cuda_runtime.h>
#include <cuda_fp16.h>
#include <math_constants.h>

typedef unsigned int u32;

#define Dd     64
#define Kk     1024
#define HW     4096
#define NPTS   65536
#define QELEMS 4194304
#define TPB    128
#define MCTA   128                // points per CTA (32 per warp, 2 m16 tiles)
#define NBLK   (NPTS / MCTA)      // 512 -> single wave at 4 CTA/SM
#define CH     8                  // groups staged per chunk
#define NCHUNK (128 / CH)         // 16
#define INV2048 4.8828125e-4f

// smem byte offsets
#define XS_STRIDE 66
#define OFF_XS   0                              // 128*66*4 = 33792
#define OFF_ESN  33792                          // 1024*4   = 4096
#define OFF_SB   37888                          // 8*256*8  = 16384
#define OFF_BIDX 54272                          // 128*4
#define OFF_RED  54784                          // 128*4
#define SMEM_TOTAL 55424

// B fragments in mma register layout: [(group*2 + split)*4 + kstep]*32 + lane
__device__ __align__(16) uint2 g_bfrag[2 * 128 * 4 * 32];
__device__ float g_en2[Kk];        // -||e_k||^2 / 2
__device__ float g_partial[NBLK];

// ---- helpers ----
// fp16 2-split: v = h + m*2^-11 (+ ~2^-22 residual); m' = (v-h)*2048 is exact
__device__ __forceinline__ float2 split2(float v) {
    float h = __half2float(__float2half_rn(v));
    float m = (v - h) * 2048.0f;     // exact: Sterbenz diff, pow2 scale
    return make_float2(h, m);
}
__device__ __forceinline__ u32 packh(float a, float b) {
    __half2 t = __floats2half2_rn(a, b);   // a -> low half
    return *reinterpret_cast<u32*>(&t);
}
__device__ __forceinline__ void mma16816(float& c0, float& c1, float& c2, float& c3,
                                         u32 a0, u32 a1, u32 a2, u32 a3,
                                         u32 b0, u32 b1) {
    asm volatile("mma.sync.aligned.m16n8k16.row.col.f32.f16.f16.f32 "
                 "{%0,%1,%2,%3}, {%4,%5,%6,%7}, {%8,%9}, {%0,%1,%2,%3};"
                 : "+f"(c0), "+f"(c1), "+f"(c2), "+f"(c3)
                 : "r"(a0), "r"(a1), "r"(a2), "r"(a3), "r"(b0), "r"(b1));
}

// ---- prep: -||e||^2/2 ----
__global__ void prep_enorm(const float* __restrict__ e) {
    int k = blockIdx.x * blockDim.x + threadIdx.x;
    if (k < Kk) {
        float s = 0.f;
        #pragma unroll
        for (int d = 0; d < Dd; d++) {
            float v = e[(size_t)d * Kk + k];
            s = fmaf(v, v, s);
        }
        g_en2[k] = -0.5f * s;
    }
}

// ---- prep: B fragments (fp16 2-split codebook, mma B-register layout) ----
__global__ void prep_frag(const float* __restrict__ e) {
    int tid = blockIdx.x * blockDim.x + threadIdx.x;   // 32768 threads
    int lane = tid & 31;
    int ks   = (tid >> 5) & 3;
    int s    = (tid >> 7) & 1;
    int grp  = tid >> 8;
    int n  = grp * 8 + (lane >> 2);
    int k0 = ks * 16 + 2 * (lane & 3);
    float2 va = split2(e[(size_t)k0 * Kk + n]);
    float2 vb = split2(e[(size_t)(k0 + 1) * Kk + n]);
    float2 vc = split2(e[(size_t)(k0 + 8) * Kk + n]);
    float2 vd = split2(e[(size_t)(k0 + 9) * Kk + n]);
    g_bfrag[tid] = (s == 0)
        ? make_uint2(packh(va.x, vb.x), packh(vc.x, vd.x))
        : make_uint2(packh(va.y, vb.y), packh(vc.y, vd.y));
}

// ---- main: 3-product fp16 mma, 2 M-tiles/warp, fused argmax(dot - ||e||^2/2) ----
__global__ __launch_bounds__(TPB, 4)
void vq_kernel(const float* __restrict__ x,
               const float* __restrict__ e,
               float* __restrict__ out,
               long long out_size) {
    extern __shared__ char smem[];
    float* xs  = (float*)(smem + OFF_XS);      // [128][66] fp32 x tile
    float* esn = (float*)(smem + OFF_ESN);     // [1024] -||e||^2/2
    uint2* sB  = (uint2*)(smem + OFF_SB);      // staged B fragment chunk
    int*   bidx= (int*)  (smem + OFF_BIDX);
    float* red = (float*)(smem + OFF_RED);

    const int t = threadIdx.x, wid = t >> 5, lane = t & 31;
    const int gr = lane >> 2, tc = lane & 3;

    // stage x tile (coalesced; CTA lies inside one batch image)
    for (int i = t; i < MCTA * Dd; i += TPB) {
        int d = i >> 7, pl = i & 127;
        int p = blockIdx.x * MCTA + pl;
        int b = p >> 12, hw = p & 4095;
        xs[pl * XS_STRIDE + d] = x[(size_t)b * (Dd * HW) + (size_t)d * HW + hw];
    }
    for (int i = t; i < Kk; i += TPB) esn[i] = g_en2[i];
    __syncthreads();

    // build A fragments: 2 tiles x 2 splits x 4 ksteps x 4 regs
    u32 A[2][2][4][4];
    #pragma unroll
    for (int tile = 0; tile < 2; tile++) {
        const int r0 = wid * 32 + tile * 16 + gr;
        #pragma unroll
        for (int ks = 0; ks < 4; ks++) {
            #pragma unroll
            for (int half = 0; half < 2; half++) {
                int k = ks * 16 + 2 * tc + half * 8;
                float2 v0 = *(float2*)&xs[r0 * XS_STRIDE + k];
                float2 v1 = *(float2*)&xs[(r0 + 8) * XS_STRIDE + k];
                float2 s0 = split2(v0.x), s1 = split2(v0.y);
                float2 s2 = split2(v1.x), s3 = split2(v1.y);
                A[tile][0][ks][2 * half + 0] = packh(s0.x, s1.x);
                A[tile][0][ks][2 * half + 1] = packh(s2.x, s3.x);
                A[tile][1][ks][2 * half + 0] = packh(s0.y, s1.y);
                A[tile][1][ks][2 * half + 1] = packh(s2.y, s3.y);
            }
        }
    }

    // best (val,idx) for rows gr, gr+8, gr+16, gr+24 (argmax of dot - ||e||^2/2)
    float bv0 = -CUDART_INF_F, bv1 = -CUDART_INF_F, bv2 = -CUDART_INF_F, bv3 = -CUDART_INF_F;
    int   bi0 = 0, bi1 = 0, bi2 = 0, bi3 = 0;

    for (int ch = 0; ch < NCHUNK; ch++) {
        __syncthreads();
        // stage B chunk: 8 groups * 256 uint2 = 1024 uint4
        {
            const uint4* src = (const uint4*)(g_bfrag + (size_t)ch * CH * 256);
            uint4* dst = (uint4*)sB;
            #pragma unroll
            for (int i = 0; i < 8; i++) dst[t + i * TPB] = src[t + i * TPB];
        }
        __syncthreads();

        #pragma unroll 2
        for (int gl = 0; gl < CH; gl++) {
            const uint2* bp = sB + gl * 256 + lane;
            u32 B0[4][2], B1[4][2];
            #pragma unroll
            for (int ks = 0; ks < 4; ks++) {
                uint2 q0 = bp[ks * 32];        B0[ks][0] = q0.x; B0[ks][1] = q0.y;
                uint2 q1 = bp[(4 + ks) * 32];  B1[ks][0] = q1.x; B1[ks][1] = q1.y;
            }
            const int g = ch * CH + gl;
            float2 ne = *(float2*)&esn[g * 8 + 2 * tc];

            // tile 0: hh accum seeded with -||e||^2/2; hm+mh share one accum
            float h0 = ne.x, h1 = ne.y, h2 = ne.x, h3 = ne.y;
            float m0 = 0.f, m1 = 0.f, m2 = 0.f, m3 = 0.f;
            #pragma unroll
            for (int ks = 0; ks < 4; ks++)
                mma16816(h0,h1,h2,h3, A[0][0][ks][0],A[0][0][ks][1],A[0][0][ks][2],A[0][0][ks][3], B0[ks][0],B0[ks][1]);
            #pragma unroll
            for (int ks = 0; ks < 4; ks++)
                mma16816(m0,m1,m2,m3, A[0][0][ks][0],A[0][0][ks][1],A[0][0][ks][2],A[0][0][ks][3], B1[ks][0],B1[ks][1]);
            #pragma unroll
            for (int ks = 0; ks < 4; ks++)
                mma16816(m0,m1,m2,m3, A[0][1][ks][0],A[0][1][ks][1],A[0][1][ks][2],A[0][1][ks][3], B0[ks][0],B0[ks][1]);

            // tile 1
            float p0 = ne.x, p1 = ne.y, p2 = ne.x, p3 = ne.y;
            float q0 = 0.f, q1 = 0.f, q2 = 0.f, q3 = 0.f;
            #pragma unroll
            for (int ks = 0; ks < 4; ks++)
                mma16816(p0,p1,p2,p3, A[1][0][ks][0],A[1][0][ks][1],A[1][0][ks][2],A[1][0][ks][3], B0[ks][0],B0[ks][1]);
            #pragma unroll
            for (int ks = 0; ks < 4; ks++)
                mma16816(q0,q1,q2,q3, A[1][0][ks][0],A[1][0][ks][1],A[1][0][ks][2],A[1][0][ks][3], B1[ks][0],B1[ks][1]);
            #pragma unroll
            for (int ks = 0; ks < 4; ks++)
                mma16816(q0,q1,q2,q3, A[1][1][ks][0],A[1][1][ks][1],A[1][1][ks][2],A[1][1][ks][3], B0[ks][0],B0[ks][1]);

            const int kg = g * 8 + 2 * tc;
            float v;
            v = fmaf(m0, INV2048, h0); if (v > bv0) { bv0 = v; bi0 = kg;     }
            v = fmaf(m1, INV2048, h1); if (v > bv0) { bv0 = v; bi0 = kg + 1; }
            v = fmaf(m2, INV2048, h2); if (v > bv1) { bv1 = v; bi1 = kg;     }
            v = fmaf(m3, INV2048, h3); if (v > bv1) { bv1 = v; bi1 = kg + 1; }
            v = fmaf(q0, INV2048, p0); if (v > bv2) { bv2 = v; bi2 = kg;     }
            v = fmaf(q1, INV2048, p1); if (v > bv2) { bv2 = v; bi2 = kg + 1; }
            v = fmaf(q2, INV2048, p2); if (v > bv3) { bv3 = v; bi3 = kg;     }
            v = fmaf(q3, INV2048, p3); if (v > bv3) { bv3 = v; bi3 = kg + 1; }
        }
    }

    // reduce over the 4-lane quad (cols); argmax, tie -> smaller index
    #pragma unroll
    for (int o = 1; o <= 2; o <<= 1) {
        float ov; int oi;
        ov = __shfl_xor_sync(0xffffffffu, bv0, o); oi = __shfl_xor_sync(0xffffffffu, bi0, o);
        if (ov > bv0 || (ov == bv0 && oi < bi0)) { bv0 = ov; bi0 = oi; }
        ov = __shfl_xor_sync(0xffffffffu, bv1, o); oi = __shfl_xor_sync(0xffffffffu, bi1, o);
        if (ov > bv1 || (ov == bv1 && oi < bi1)) { bv1 = ov; bi1 = oi; }
        ov = __shfl_xor_sync(0xffffffffu, bv2, o); oi = __shfl_xor_sync(0xffffffffu, bi2, o);
        if (ov > bv2 || (ov == bv2 && oi < bi2)) { bv2 = ov; bi2 = oi; }
        ov = __shfl_xor_sync(0xffffffffu, bv3, o); oi = __shfl_xor_sync(0xffffffffu, bi3, o);
        if (ov > bv3 || (ov == bv3 && oi < bi3)) { bv3 = ov; bi3 = oi; }
    }
    if (tc == 0) {
        const int rb = wid * 32 + gr;
        bidx[rb]      = bi0;
        bidx[rb + 8]  = bi1;
        bidx[rb + 16] = bi2;
        bidx[rb + 24] = bi3;
    }
    __syncthreads();

    // epilogue: quantized gather + index + loss partial (exact fp32)
    float lsum = 0.f;
    {
        int p = blockIdx.x * MCTA + t;
        int b = p >> 12, hw = p & 4095;
        size_t xbase = (size_t)b * (Dd * HW) + hw;
        int k = bidx[t];
        #pragma unroll
        for (int d = 0; d < Dd; d++) {
            float q = e[(size_t)d * Kk + k];
            long long o = (long long)(xbase + (size_t)d * HW);
            if (o < out_size) out[o] = q;
            float df = xs[t * XS_STRIDE + d] - q;
            lsum = fmaf(df, df, lsum);
        }
        long long io = (long long)QELEMS + 2 + p;
        if (io < out_size) out[io] = (float)k;
    }
    red[t] = lsum;
    __syncthreads();
    #pragma unroll
    for (int sft = TPB / 2; sft > 0; sft >>= 1) {
        if (t < sft) red[t] += red[t + sft];
        __syncthreads();
    }
    if (t == 0) g_partial[blockIdx.x] = red[0];
}

// parallel deterministic loss reduction: fixed-order tree in double
__global__ void loss_kernel(float* __restrict__ out, long long out_size) {
    __shared__ double sred[256];
    int t = threadIdx.x;
    double s = 0.0;
    #pragma unroll
    for (int i = 0; i < NBLK / 256; i++)
        s += (double)g_partial[t + i * 256];
    sred[t] = s;
    __syncthreads();
    #pragma unroll
    for (int sft = 128; sft > 0; sft >>= 1) {
        if (t < sft) sred[t] += sred[t + sft];
        __syncthreads();
    }
    if (t == 0) {
        float mean = (float)(sred[0] / (double)QELEMS);
        long long off = (long long)QELEMS;
        if (off     < out_size) out[off]     = mean;  // dictionary_loss
        if (off + 1 < out_size) out[off + 1] = mean;  // commitment_loss
    }
}

extern "C" void kernel_launch(void* const* d_in, const int* in_sizes, int n_in,
                              void* d_out, int out_size) {
    const float* x = (const float*)d_in[0];
    const float* e = (const float*)d_in[1];
    if (n_in >= 2 && in_sizes[0] == Dd * Kk && in_sizes[1] == QELEMS) {
        const float* tmp = x; x = e; e = tmp;
    }
    float* out = (float*)d_out;
    long long osz = (long long)out_size;

    cudaFuncSetAttribute(vq_kernel, cudaFuncAttributeMaxDynamicSharedMemorySize, SMEM_TOTAL);
    prep_enorm<<<8, 128>>>(e);
    prep_frag<<<256, 128>>>(e);
    vq_kernel<<<NBLK, TPB, SMEM_TOTAL>>>(x, e, out, osz);
    loss_kernel<<<1, 256>>>(out, osz);
}